// round 12
// baseline (speedup 1.0000x reference)
#include <cuda_runtime.h>

// GraphSAGE 2-layer, N=100000, E=1600000, dims 32 -> 64 -> 32.
// CSR (dst-sorted) + EDGE-PARALLEL SEGMENTED gathers (shfl-reduced, few atomics):
//   Z : zero g_agg + deg
//   C : count deg[dst]++
//   SA: per-chunk partial sums (98 blocks)
//   SC: per-chunk exclusive scan (each block also reduces partials) -> off, cur
//   F : fill adj2[cur[dst]++] = {src, dst}
//   G1: segmented gather  g_agg[d] += x[s]     (warp = 4 CSR slots, head-only v4 RED)
//   M : fused MLP (thread/node, FFMA2): h=relu(W1l@agg+b1+W1r@x); g=W2l@h; out=W2r@h+b2
//   G2: segmented gather  out[d] += g_g[s]
// Layer-2 projection applied BEFORE aggregation (linear commutes with sum).
// edge_index is int32 on device.

#define NN 100000
#define EE 1600000
#define D 32
#define CHUNK 1024
#define NB ((NN + CHUNK - 1) / CHUNK)        // 98
#define NPAD (NB * CHUNK)                    // 100352

typedef unsigned long long ull;

__device__ int   g_deg[NPAD];
__device__ int   g_part[NB];
__device__ int   g_off[NN + 1];
__device__ int   g_cur[NN];
__device__ int2  g_adj2[EE];                 // {src, dst}, sorted by dst
__device__ float g_agg[NN * D];
__device__ float g_g[NN * D];

__device__ __forceinline__ void red_add_v4(float* addr, float4 v) {
    asm volatile("red.global.add.v4.f32 [%0], {%1, %2, %3, %4};"
                 :: "l"(addr), "f"(v.x), "f"(v.y), "f"(v.z), "f"(v.w)
                 : "memory");
}
__device__ __forceinline__ ull fma2(ull a, ull b, ull c) {
    ull d;
    asm("fma.rn.f32x2 %0, %1, %2, %3;" : "=l"(d) : "l"(a), "l"(b), "l"(c));
    return d;
}
__device__ __forceinline__ ull pack2(float lo, float hi) {
    ull d;
    asm("mov.b64 %0, {%1, %2};" : "=l"(d) : "f"(lo), "f"(hi));
    return d;
}
__device__ __forceinline__ void unpack2(ull v, float& lo, float& hi) {
    asm("mov.b64 {%0, %1}, %2;" : "=f"(lo), "=f"(hi) : "l"(v));
}

// ---------------------------------------------------------------------------
__global__ void zeros_kernel() {
    int i = blockIdx.x * blockDim.x + threadIdx.x;
    if (i < NN * D / 4) ((float4*)g_agg)[i] = make_float4(0.f, 0.f, 0.f, 0.f);
    if (i < NPAD / 4)   ((int4*)g_deg)[i] = make_int4(0, 0, 0, 0);
}

__global__ void count_kernel(const int* __restrict__ dst, int E) {
    int e = blockIdx.x * blockDim.x + threadIdx.x;
    if (e < E) atomicAdd(&g_deg[dst[e]], 1);
}

// scanA: per-chunk total. grid=NB, block=256, each thread sums 4 via int4.
__global__ void scanA_kernel() {
    __shared__ int ws[8];
    int c = blockIdx.x, t = threadIdx.x;
    int4 v = ((const int4*)g_deg)[c * 256 + t];
    int s = v.x + v.y + v.z + v.w;
    #pragma unroll
    for (int o = 16; o; o >>= 1) s += __shfl_xor_sync(0xffffffffu, s, o);
    if ((t & 31) == 0) ws[t >> 5] = s;
    __syncthreads();
    if (t == 0) {
        int tot = 0;
        #pragma unroll
        for (int i = 0; i < 8; i++) tot += ws[i];
        g_part[c] = tot;
    }
}

// scanC: block c reduces partials[0..c) itself, then per-chunk exclusive scan.
__global__ void scanC_kernel(int E) {
    __shared__ int wsA[8];
    __shared__ int wsB[8];
    __shared__ int s_base;
    int c = blockIdx.x, t = threadIdx.x;
    int lane = t & 31, w = t >> 5;

    // 1) base = sum of g_part[0..c)
    int pv = (t < c) ? g_part[t] : 0;        // c < NB <= 98 < 256
    int sr = pv;
    #pragma unroll
    for (int o = 16; o; o >>= 1) sr += __shfl_xor_sync(0xffffffffu, sr, o);
    if (lane == 0) wsA[w] = sr;
    __syncthreads();
    if (t == 0) {
        int tot = 0;
        #pragma unroll
        for (int i = 0; i < 8; i++) tot += wsA[i];
        s_base = tot;
    }
    __syncthreads();

    // 2) per-chunk exclusive scan
    int base = c * CHUNK + t * 4;
    int4 v = ((const int4*)g_deg)[c * 256 + t];
    int tsum = v.x + v.y + v.z + v.w;
    int incl = tsum;
    #pragma unroll
    for (int o = 1; o < 32; o <<= 1) {
        int n = __shfl_up_sync(0xffffffffu, incl, o);
        if (lane >= o) incl += n;
    }
    if (lane == 31) wsB[w] = incl;
    __syncthreads();
    if (w == 0) {
        int xx = (lane < 8) ? wsB[lane] : 0;
        #pragma unroll
        for (int o = 1; o < 8; o <<= 1) {
            int n = __shfl_up_sync(0xffffffffu, xx, o);
            if (lane >= o) xx += n;
        }
        if (lane < 8) wsB[lane] = xx;           // inclusive warp-total scan
    }
    __syncthreads();
    int excl = incl - tsum + (w > 0 ? wsB[w - 1] : 0) + s_base;
    int o0 = excl, o1 = o0 + v.x, o2 = o1 + v.y, o3 = o2 + v.z;
    if (base < NN)     { g_off[base]     = o0; g_cur[base]     = o0; }
    if (base + 1 < NN) { g_off[base + 1] = o1; g_cur[base + 1] = o1; }
    if (base + 2 < NN) { g_off[base + 2] = o2; g_cur[base + 2] = o2; }
    if (base + 3 < NN) { g_off[base + 3] = o3; g_cur[base + 3] = o3; }
    if (c == 0 && t == 0) g_off[NN] = E;
}

__global__ void fill_kernel(const int* __restrict__ src,
                            const int* __restrict__ dst, int E) {
    int e = blockIdx.x * blockDim.x + threadIdx.x;
    if (e >= E) return;
    int dd = dst[e];
    int pos = atomicAdd(&g_cur[dd], 1);
    g_adj2[pos] = make_int2(src[e], dd);
}

// ---------------------------------------------------------------------------
// Segmented gather: warp covers 4 consecutive CSR slots (dst-sorted).
// 8 threads/edge, each a float4 of the source row. 2-round shfl segmented
// reduction merges equal-dst runs; only segment heads issue a v4 RED.
__device__ __forceinline__ void seg_gather(const float* __restrict__ SRC,
                                           float* __restrict__ DST, int E) {
    int w = (blockIdx.x * blockDim.x + threadIdx.x) >> 5;
    int lane = threadIdx.x & 31;
    int base = w * 4;
    if (base >= E) return;

    int eg = lane >> 3;             // edge group 0..3
    int f  = (lane & 7) << 2;       // float offset 0,4,...,28
    int slot = base + eg;
    bool valid = slot < E;

    int2 sd = valid ? __ldg(&g_adj2[slot]) : make_int2(0, -1);
    int d = sd.y;
    float4 v = make_float4(0.f, 0.f, 0.f, 0.f);
    if (valid) v = *(const float4*)&SRC[sd.x * D + f];

    // backward-inclusive segmented sum over edge groups (stride 8 lanes)
    #pragma unroll
    for (int o = 8; o <= 16; o <<= 1) {
        int nd = __shfl_down_sync(0xffffffffu, d, o);
        float nx = __shfl_down_sync(0xffffffffu, v.x, o);
        float ny = __shfl_down_sync(0xffffffffu, v.y, o);
        float nz = __shfl_down_sync(0xffffffffu, v.z, o);
        float nw = __shfl_down_sync(0xffffffffu, v.w, o);
        if ((lane + o < 32) && (nd == d)) {
            v.x += nx; v.y += ny; v.z += nz; v.w += nw;
        }
    }
    int pd = __shfl_up_sync(0xffffffffu, d, 8);
    bool head = valid && ((lane < 8) || (pd != d));
    if (head) red_add_v4(&DST[d * D + f], v);
}

__global__ void gather_x_kernel(const float* __restrict__ x, int E) {
    seg_gather(x, g_agg, E);
}
__global__ void gather_g_kernel(float* __restrict__ out, int E) {
    seg_gather(g_g, out, E);
}

// ---------------------------------------------------------------------------
// Thread-per-node MLP with f32x2 packed FMA (unchanged from R6 best).
__global__ void __launch_bounds__(128)
fused_mlp_kernel(const float* __restrict__ x,
                 const float* __restrict__ Wli,  // [64,32]
                 const float* __restrict__ bli,  // [64]
                 const float* __restrict__ Wri,  // [64,32]
                 const float* __restrict__ Wlo,  // [32,64]
                 const float* __restrict__ blo,  // [32]
                 const float* __restrict__ Wro,  // [32,64]
                 float* __restrict__ out,
                 int N) {
    __shared__ longlong2 w1l[32][16];
    __shared__ longlong2 w1r[32][16];
    __shared__ longlong2 w2l[64][8];
    __shared__ longlong2 w2r[64][8];
    __shared__ ull b1p[32];
    __shared__ ull b2p[16];

    int tid = threadIdx.x;
    {
        float* W1L = (float*)w1l;
        float* W1R = (float*)w1r;
        float* W2L = (float*)w2l;
        float* W2R = (float*)w2r;
        for (int idx = tid; idx < 2048; idx += 128) {
            int k = idx >> 6, m = idx & 63;
            W1L[k * 64 + m] = Wli[m * 32 + k];
            W1R[k * 64 + m] = Wri[m * 32 + k];
            int mm = idx >> 5, o = idx & 31;
            W2L[mm * 32 + o] = Wlo[o * 64 + mm];
            W2R[mm * 32 + o] = Wro[o * 64 + mm];
        }
        if (tid < 64) ((float*)b1p)[tid] = bli[tid];
        if (tid < 32) ((float*)b2p)[tid] = blo[tid];
    }
    __syncthreads();

    int node = blockIdx.x * 128 + tid;
    if (node >= N) return;

    float a[32], xv[32];
    {
        const float4* ar = (const float4*)&g_agg[node * D];
        const float4* xr = (const float4*)&x[node * D];
        #pragma unroll
        for (int i = 0; i < 8; i++) {
            float4 t0 = ar[i];
            a[4 * i] = t0.x; a[4 * i + 1] = t0.y; a[4 * i + 2] = t0.z; a[4 * i + 3] = t0.w;
            float4 t1 = xr[i];
            xv[4 * i] = t1.x; xv[4 * i + 1] = t1.y; xv[4 * i + 2] = t1.z; xv[4 * i + 3] = t1.w;
        }
    }

    ull h2[32];
    #pragma unroll
    for (int m2 = 0; m2 < 32; m2++) h2[m2] = b1p[m2];

    #pragma unroll
    for (int k = 0; k < 32; k++) {
        ull av2 = pack2(a[k], a[k]);
        ull xx2 = pack2(xv[k], xv[k]);
        #pragma unroll
        for (int q = 0; q < 16; q++) {
            longlong2 wl = w1l[k][q];
            longlong2 wr = w1r[k][q];
            h2[2 * q]     = fma2((ull)wl.x, av2, h2[2 * q]);
            h2[2 * q + 1] = fma2((ull)wl.y, av2, h2[2 * q + 1]);
            h2[2 * q]     = fma2((ull)wr.x, xx2, h2[2 * q]);
            h2[2 * q + 1] = fma2((ull)wr.y, xx2, h2[2 * q + 1]);
        }
    }

    float hs[64];
    #pragma unroll
    for (int m2 = 0; m2 < 32; m2++) {
        float lo, hi;
        unpack2(h2[m2], lo, hi);
        hs[2 * m2]     = fmaxf(lo, 0.0f);
        hs[2 * m2 + 1] = fmaxf(hi, 0.0f);
    }

    ull g2[16], r2[16];
    #pragma unroll
    for (int o2 = 0; o2 < 16; o2++) { g2[o2] = 0ull; r2[o2] = b2p[o2]; }

    #pragma unroll
    for (int m = 0; m < 64; m++) {
        ull hv2 = pack2(hs[m], hs[m]);
        #pragma unroll
        for (int q = 0; q < 8; q++) {
            longlong2 wl = w2l[m][q];
            longlong2 wr = w2r[m][q];
            g2[2 * q]     = fma2((ull)wl.x, hv2, g2[2 * q]);
            g2[2 * q + 1] = fma2((ull)wl.y, hv2, g2[2 * q + 1]);
            r2[2 * q]     = fma2((ull)wr.x, hv2, r2[2 * q]);
            r2[2 * q + 1] = fma2((ull)wr.y, hv2, r2[2 * q + 1]);
        }
    }

    ull* gg = (ull*)&g_g[node * D];
    ull* oo = (ull*)&out[node * D];
    #pragma unroll
    for (int o2 = 0; o2 < 16; o2++) {
        gg[o2] = g2[o2];
        oo[o2] = r2[o2];
    }
}

// ---------------------------------------------------------------------------
extern "C" void kernel_launch(void* const* d_in, const int* in_sizes, int n_in,
                              void* d_out, int out_size) {
    const float* x   = (const float*)d_in[0];
    const int*   ei  = (const int*)d_in[1];
    const float* Wli = (const float*)d_in[2];
    const float* bli = (const float*)d_in[3];
    const float* Wri = (const float*)d_in[4];
    const float* Wlo = (const float*)d_in[5];
    const float* blo = (const float*)d_in[6];
    const float* Wro = (const float*)d_in[7];
    float* out = (float*)d_out;

    int N = in_sizes[0] / D;      // 100000
    int E = in_sizes[1] / 2;      // 1600000
    const int* src = ei;
    const int* dst = ei + E;

    // CSR build (per call)
    zeros_kernel<<<(NN * D / 4 + 255) / 256, 256>>>();
    count_kernel<<<(E + 255) / 256, 256>>>(dst, E);
    scanA_kernel<<<NB, 256>>>();
    scanC_kernel<<<NB, 256>>>(E);
    fill_kernel<<<(E + 255) / 256, 256>>>(src, dst, E);

    // Edge-parallel segmented aggregation + fused MLP
    int gblocks = ((E + 3) / 4 * 32 + 255) / 256;   // warp per 4 CSR slots
    gather_x_kernel<<<gblocks, 256>>>(x, E);
    fused_mlp_kernel<<<(N + 127) / 128, 128>>>(x, Wli, bli, Wri, Wlo, blo, Wro, out, N);
    gather_g_kernel<<<gblocks, 256>>>(out, E);
}